// round 4
// baseline (speedup 1.0000x reference)
#include <cuda_runtime.h>

// SetConv on GB300 — Round 1: separable-exp fp32 baseline.
//
// z_grid[b,i,j,:] = sum_n Ex[b,i,n] * Ey[b,j,n] * z[b,n,:]
// Ex/Ey precomputed (2M exps instead of 134M in-loop exps).
//
// Output buffer layout (tuple concat): [ x_grid : B*M*2 ][ z_grid : B*M*DZ ]

#define BB 4
#define NN 2048
#define DZ 128
#define GG 128           // grid points per dim
#define MM (GG*GG)       // 16384
#define JT 64            // j-tile per CTA
#define NK 32            // n-chunk

// Scratch: factorized Gaussian weights. 4 MB each.
__device__ float g_Ex[BB*GG*NN];
__device__ float g_Ey[BB*GG*NN];

// ---------------------------------------------------------------------------
// Kernel 1: precompute Ex[b,i,n] = exp(-0.5*(gx_i - x[b,n,0])^2 / lx^2)
//           and     Ey[b,j,n] = exp(-0.5*(gy_j - x[b,n,1])^2 / ly^2)
// ---------------------------------------------------------------------------
__global__ void precompute_exp(const float* __restrict__ x,
                               const float* __restrict__ grid,
                               const float* __restrict__ lsp) {
    int idx = blockIdx.x * blockDim.x + threadIdx.x;
    const int total = 2 * BB * GG * NN;
    if (idx >= total) return;
    int dim = idx / (BB * GG * NN);          // 0 -> Ex, 1 -> Ey
    int r   = idx % (BB * GG * NN);
    int b   = r / (GG * NN);
    int r2  = r % (GG * NN);
    int g   = r2 / NN;
    int n   = r2 % NN;

    float p   = lsp[dim];
    float l   = 1e-5f + log1pf(expf(p));     // softplus + eps
    float inv = 1.0f / (l * l);

    // grid[i][j][c] at (i*GG + j)*2 + c ; axis0 value at j=0, axis1 at i=0
    float gv = (dim == 0) ? grid[(g * GG) * 2 + 0] : grid[g * 2 + 1];
    float xv = x[(b * NN + n) * 2 + dim];
    float d  = gv - xv;
    float e  = expf(-0.5f * d * d * inv);
    (dim == 0 ? g_Ex : g_Ey)[r] = e;
}

// ---------------------------------------------------------------------------
// Kernel 2: x_grid output = broadcast of grid over batch
// ---------------------------------------------------------------------------
__global__ void fill_xgrid(const float* __restrict__ grid,
                           float* __restrict__ out) {
    int idx = blockIdx.x * blockDim.x + threadIdx.x;
    const int total = BB * MM * 2;
    if (idx >= total) return;
    out[idx] = grid[idx % (MM * 2)];
}

// ---------------------------------------------------------------------------
// Kernel 3: main contraction.
// CTA = (jtile, i, b): 64 j-rows x 128 dz columns, loop n in chunks of 32.
// Thread layout: dgrp = t&31 owns 4 consecutive dz (float4),
//                jgrp = t>>5 owns 8 j rows. 32 fp32 accumulators/thread.
// All ex/ey smem reads are warp-broadcast; z reads are conflict-free float4.
// ---------------------------------------------------------------------------
__global__ void __launch_bounds__(256)
setconv_main(const float* __restrict__ z, float* __restrict__ out) {
    __shared__ float4 z_s[NK][DZ / 4];   // 16 KB
    __shared__ float  ey_s[JT][NK];      // 8 KB
    __shared__ float  ex_s[NK];

    const int b  = blockIdx.z;
    const int i  = blockIdx.y;
    const int j0 = blockIdx.x * JT;
    const int t  = threadIdx.x;
    const int dgrp = t & 31;
    const int jgrp = t >> 5;

    float4 acc[8];
#pragma unroll
    for (int r = 0; r < 8; r++) acc[r] = make_float4(0.f, 0.f, 0.f, 0.f);

    const float*  exrow  = g_Ex + ((size_t)b * GG + i) * NN;
    const float*  eybase = g_Ey + ((size_t)b * GG + j0) * NN;
    const float4* zb     = (const float4*)(z + (size_t)b * NN * DZ);

    for (int n0 = 0; n0 < NN; n0 += NK) {
        // stage z chunk [NK][DZ] as float4 (coalesced)
#pragma unroll
        for (int idx = t; idx < NK * (DZ / 4); idx += 256) {
            int k = idx >> 5, dg = idx & 31;
            z_s[k][dg] = zb[(size_t)(n0 + k) * (DZ / 4) + dg];
        }
        // stage ey [JT][NK] (rows contiguous in n -> coalesced)
#pragma unroll
        for (int idx = t; idx < JT * NK; idx += 256) {
            int jl = idx >> 5, k = idx & 31;
            ey_s[jl][k] = eybase[(size_t)jl * NN + n0 + k];
        }
        if (t < NK) ex_s[t] = exrow[n0 + t];
        __syncthreads();

#pragma unroll 8
        for (int k = 0; k < NK; k++) {
            float  exk = ex_s[k];
            float4 z4  = z_s[k][dgrp];
#pragma unroll
            for (int r = 0; r < 8; r++) {
                float w = exk * ey_s[jgrp * 8 + r][k];
                acc[r].x += w * z4.x;
                acc[r].y += w * z4.y;
                acc[r].z += w * z4.z;
                acc[r].w += w * z4.w;
            }
        }
        __syncthreads();
    }

    // store z_grid tile: out[((b*GG+i)*GG + j)*DZ + d]
    float4* ob = (float4*)(out + ((size_t)((b * GG + i) * GG) + j0) * DZ);
#pragma unroll
    for (int r = 0; r < 8; r++) {
        int jl = jgrp * 8 + r;
        ob[(size_t)jl * (DZ / 4) + dgrp] = acc[r];
    }
}

// ---------------------------------------------------------------------------
extern "C" void kernel_launch(void* const* d_in, const int* in_sizes, int n_in,
                              void* d_out, int out_size) {
    const float* x    = (const float*)d_in[0];   // [B,N,2]
    const float* z    = (const float*)d_in[1];   // [B,N,128]
    const float* grid = (const float*)d_in[2];   // [128,128,2]
    const float* lsp  = (const float*)d_in[3];   // [2]
    float* out = (float*)d_out;

    (void)in_sizes; (void)n_in; (void)out_size;

    const int tot_exp = 2 * BB * GG * NN;
    precompute_exp<<<(tot_exp + 255) / 256, 256>>>(x, grid, lsp);

    const int tot_xg = BB * MM * 2;
    fill_xgrid<<<(tot_xg + 255) / 256, 256>>>(grid, out);

    dim3 g(GG / JT, GG, BB);   // (2, 128, 4)
    setconv_main<<<g, 256>>>(z, out + (size_t)BB * MM * 2);
}

// round 10
// speedup vs baseline: 2.6225x; 2.6225x over previous
#include <cuda_runtime.h>
#include <cuda_bf16.h>
#include <cstdint>

// SetConv on GB300 — Round 9: HMMA (mma.sync bf16) split-precision version.
// tcgen05 is unavailable (harness lowers via compute_103: ptxas rejects all
// tcgen05/.cta_group features). Use sm_80-era ldmatrix + mma.sync.m16n8k16
// bf16 with hi/lo split on both operands, 3 passes, fp32 accumulators.
//
// z_grid[b,i,j,d] = sum_n Ex[b,i,n] * Ey[b,j,n] * z[b,n,d]
// Per CTA (b,i): D[128x128] = A'(Ey*Ex_i)[128j x 2048n] @ zT[128d x 2048n]^T
//
// Output: [ x_grid : B*M*2 ][ z_grid : B*M*DZ ]

#define BB 4
#define NN 2048
#define DZ 128
#define GG 128
#define MM (GG*GG)
#define KCH 32                 // n per chunk
#define NCHUNK (NN/KCH)        // 64
#define ROWB 80                // padded smem row stride (64B data + 16B pad)
#define BUFB 40960             // bytes per double-buffer slot (4 tiles x 10240)
#define SMEM_BYTES (2*BUFB)    // 81920

// ---- scratch (no allocs allowed) ----
__device__ float         g_Ex[BB*GG*NN];     // [b][i][n]
__device__ float         g_Ey[BB*GG*NN];     // [b][j][n]
__device__ __nv_bfloat16 g_zthi[BB*DZ*NN];   // [b][d][n]
__device__ __nv_bfloat16 g_ztlo[BB*DZ*NN];

// ---------------------------------------------------------------------------
// helpers
// ---------------------------------------------------------------------------
__device__ __forceinline__ uint32_t smem_u32(const void* p) {
    uint32_t a;
    asm("{ .reg .u64 t; cvta.to.shared.u64 t, %1; cvt.u32.u64 %0, t; }"
        : "=r"(a) : "l"(p));
    return a;
}
__device__ __forceinline__ void ldsm4(uint32_t* r, uint32_t addr) {
    asm volatile("ldmatrix.sync.aligned.m8n8.x4.shared.b16 {%0,%1,%2,%3}, [%4];"
                 : "=r"(r[0]), "=r"(r[1]), "=r"(r[2]), "=r"(r[3]) : "r"(addr));
}
__device__ __forceinline__ void mma_bf16(float* c, const uint32_t* a,
                                         const uint32_t* b) {
    asm volatile(
        "mma.sync.aligned.m16n8k16.row.col.f32.bf16.bf16.f32 "
        "{%0,%1,%2,%3}, {%4,%5,%6,%7}, {%8,%9}, {%0,%1,%2,%3};"
        : "+f"(c[0]), "+f"(c[1]), "+f"(c[2]), "+f"(c[3])
        : "r"(a[0]), "r"(a[1]), "r"(a[2]), "r"(a[3]), "r"(b[0]), "r"(b[1]));
}
__device__ __forceinline__ void cp16(uint32_t dst, const void* src) {
    asm volatile("cp.async.cg.shared.global [%0], [%1], 16;"
                 :: "r"(dst), "l"(src) : "memory");
}

// ---------------------------------------------------------------------------
// Prep 1: Ex[b,i,n], Ey[b,j,n] (fp32)
// ---------------------------------------------------------------------------
__global__ void precompute_exp(const float* __restrict__ x,
                               const float* __restrict__ grid,
                               const float* __restrict__ lsp) {
    int idx = blockIdx.x * blockDim.x + threadIdx.x;
    const int total = 2 * BB * GG * NN;
    if (idx >= total) return;
    int dim = idx / (BB * GG * NN);
    int r   = idx % (BB * GG * NN);
    int b   = r / (GG * NN);
    int r2  = r % (GG * NN);
    int g   = r2 / NN;
    int n   = r2 % NN;

    float p   = lsp[dim];
    float l   = 1e-5f + log1pf(expf(p));
    float inv = 1.0f / (l * l);
    float gv  = (dim == 0) ? grid[(g * GG) * 2 + 0] : grid[g * 2 + 1];
    float xv  = x[(b * NN + n) * 2 + dim];
    float d   = gv - xv;
    float e   = expf(-0.5f * d * d * inv);
    (dim == 0 ? g_Ex : g_Ey)[r] = e;
}

// ---------------------------------------------------------------------------
// Prep 2: transpose z -> zT[b][d][n], split bf16 hi/lo
// ---------------------------------------------------------------------------
__global__ void zt_split(const float* __restrict__ z) {
    __shared__ float tl[32][33];
    int b  = blockIdx.z;
    int n0 = blockIdx.x * 32;
    int d0 = blockIdx.y * 32;
    int tx = threadIdx.x, ty = threadIdx.y;

    tl[ty][tx] = z[((size_t)(b * NN + n0 + ty)) * DZ + d0 + tx];
    __syncthreads();
    float v = tl[tx][ty];
    __nv_bfloat16 h  = __float2bfloat16(v);
    __nv_bfloat16 lo = __float2bfloat16(v - __bfloat162float(h));
    size_t o = ((size_t)(b * DZ + d0 + ty)) * NN + n0 + tx;
    g_zthi[o] = h;
    g_ztlo[o] = lo;
}

// ---------------------------------------------------------------------------
// Prep 3: x_grid = broadcast grid over batch
// ---------------------------------------------------------------------------
__global__ void fill_xgrid(const float* __restrict__ grid, float* __restrict__ out) {
    int idx = blockIdx.x * blockDim.x + threadIdx.x;
    const int total = BB * MM * 2;
    if (idx >= total) return;
    out[idx] = grid[idx % (MM * 2)];
}

// ---------------------------------------------------------------------------
// Main HMMA kernel. One CTA per (b, i). 8 warps (4x2), warp tile 32x64.
// smem buffer slot layout: [AH 10240][AL 10240][BH 10240][BL 10240]
// ---------------------------------------------------------------------------
__global__ void __launch_bounds__(256, 2)
setconv_hmma(float* __restrict__ out_z) {
    extern __shared__ char smem[];
    const uint32_t smb = smem_u32(smem);
    const int t    = threadIdx.x;
    const int lane = t & 31;
    const int wid  = t >> 5;
    const int wm   = wid & 3;          // row block:  m0 = wm*32
    const int wn   = wid >> 2;         // col block:  d0 = wn*64
    const int b    = blockIdx.y;
    const int i    = blockIdx.x;

    float acc[2][8][4];
#pragma unroll
    for (int mt = 0; mt < 2; mt++)
#pragma unroll
        for (int nt = 0; nt < 8; nt++)
#pragma unroll
            for (int q = 0; q < 4; q++) acc[mt][nt][q] = 0.f;

    const float* exrow = g_Ex + ((size_t)(b * GG + i)) * NN;

    // ldmatrix per-lane address components
    const int arow = (lane & 7) + ((lane >> 3) & 1) * 8;   // A: bit3 -> +8 rows
    const int akof = ((lane >> 4) & 1) * 8;                // A: bit4 -> +8 k
    const int brow = (lane & 7) + ((lane >> 4) & 1) * 8;   // B: bit4 -> +8 rows
    const int bkof = ((lane >> 3) & 1) * 8;                // B: bit3 -> +8 k

    // ---- staging (lambda-free, used twice) ----
#define STAGE(cc)                                                              \
    do {                                                                       \
        const int n0s = (cc) * KCH;                                            \
        char* bufc = smem + ((cc) & 1) * BUFB;                                 \
        const uint32_t bufu = smb + ((cc) & 1) * BUFB;                         \
        _Pragma("unroll")                                                      \
        for (int p = 0; p < 8; p++) {                                          \
            int w   = t + p * 256;          /* 0..2047 */                      \
            int row = w >> 4;                                                  \
            int kw  = w & 15;                                                  \
            float2 ey2 = *(const float2*)(g_Ey +                               \
                ((size_t)(b * GG + row)) * NN + n0s + 2 * kw);                 \
            float2 ex2 = *(const float2*)(exrow + n0s + 2 * kw);               \
            float pa = ey2.x * ex2.x, pb = ey2.y * ex2.y;                      \
            __nv_bfloat162 hi2 = __float22bfloat162_rn(make_float2(pa, pb));   \
            float2 hf = __bfloat1622float2(hi2);                               \
            __nv_bfloat162 lo2 =                                               \
                __float22bfloat162_rn(make_float2(pa - hf.x, pb - hf.y));      \
            uint32_t off = (uint32_t)(row * ROWB + kw * 4);                    \
            *(__nv_bfloat162*)(bufc + off)         = hi2;                      \
            *(__nv_bfloat162*)(bufc + 10240 + off) = lo2;                      \
        }                                                                      \
        _Pragma("unroll")                                                      \
        for (int p = 0; p < 2; p++) {                                          \
            int w   = t + p * 256;          /* 0..511 */                       \
            int row = w >> 2;                                                  \
            int c4  = w & 3;                                                   \
            uint32_t doff = bufu + 20480u + (uint32_t)(row * ROWB + c4 * 16);  \
            size_t zo = ((size_t)(b * DZ + row)) * NN + n0s;                   \
            cp16(doff,          (const char*)(g_zthi + zo) + c4 * 16);         \
            cp16(doff + 10240u, (const char*)(g_ztlo + zo) + c4 * 16);         \
        }                                                                      \
        asm volatile("cp.async.commit_group;" ::: "memory");                   \
    } while (0)

    STAGE(0);

    for (int c = 0; c < NCHUNK; c++) {
        asm volatile("cp.async.wait_group 0;" ::: "memory");
        __syncthreads();
        if (c + 1 < NCHUNK) STAGE(c + 1);

        const uint32_t base = smb + (c & 1) * BUFB;
        const uint32_t AHb = base, ALb = base + 10240u;
        const uint32_t BHb = base + 20480u, BLb = base + 30720u;

#pragma unroll
        for (int ks = 0; ks < 2; ks++) {
            const int k0 = ks * 16;
            uint32_t ah[2][4], al[2][4];
#pragma unroll
            for (int mt = 0; mt < 2; mt++) {
                uint32_t aoff =
                    (uint32_t)((wm * 32 + mt * 16 + arow) * ROWB +
                               (k0 + akof) * 2);
                ldsm4(ah[mt], AHb + aoff);
                ldsm4(al[mt], ALb + aoff);
            }
#pragma unroll
            for (int ntp = 0; ntp < 4; ntp++) {
                uint32_t boff =
                    (uint32_t)((wn * 64 + ntp * 16 + brow) * ROWB +
                               (k0 + bkof) * 2);
                uint32_t bh[4], bl[4];
                ldsm4(bh, BHb + boff);
                ldsm4(bl, BLb + boff);
#pragma unroll
                for (int mt = 0; mt < 2; mt++) {
#pragma unroll
                    for (int sub = 0; sub < 2; sub++) {
                        float* cc4 = acc[mt][ntp * 2 + sub];
                        mma_bf16(cc4, ah[mt], bh + sub * 2);
                        mma_bf16(cc4, ah[mt], bl + sub * 2);
                        mma_bf16(cc4, al[mt], bh + sub * 2);
                    }
                }
            }
        }
    }

    // ---- epilogue: direct STG.64 of fp32 accumulators ----
    const size_t obase = ((size_t)(b * GG + i)) * GG * DZ;
    const int g  = lane >> 2;
    const int tq = lane & 3;
#pragma unroll
    for (int mt = 0; mt < 2; mt++) {
#pragma unroll
        for (int nt = 0; nt < 8; nt++) {
            int row0 = wm * 32 + mt * 16 + g;
            int col  = wn * 64 + nt * 8 + tq * 2;
            float* cc4 = acc[mt][nt];
            *(float2*)(out_z + obase + (size_t)row0 * DZ + col) =
                make_float2(cc4[0], cc4[1]);
            *(float2*)(out_z + obase + (size_t)(row0 + 8) * DZ + col) =
                make_float2(cc4[2], cc4[3]);
        }
    }
#undef STAGE
}

// ---------------------------------------------------------------------------
extern "C" void kernel_launch(void* const* d_in, const int* in_sizes, int n_in,
                              void* d_out, int out_size) {
    const float* x    = (const float*)d_in[0];   // [B,N,2]
    const float* z    = (const float*)d_in[1];   // [B,N,128]
    const float* grid = (const float*)d_in[2];   // [128,128,2]
    const float* lsp  = (const float*)d_in[3];   // [2]
    float* out = (float*)d_out;
    (void)in_sizes; (void)n_in; (void)out_size;

    cudaFuncSetAttribute(setconv_hmma,
        cudaFuncAttributeMaxDynamicSharedMemorySize, SMEM_BYTES);

    const int tot_exp = 2 * BB * GG * NN;
    precompute_exp<<<(tot_exp + 255) / 256, 256>>>(x, grid, lsp);

    zt_split<<<dim3(NN / 32, DZ / 32, BB), dim3(32, 32)>>>(z);

    const int tot_xg = BB * MM * 2;
    fill_xgrid<<<(tot_xg + 255) / 256, 256>>>(grid, out);

    setconv_hmma<<<dim3(GG, BB), 256, SMEM_BYTES>>>(
        out + (size_t)BB * MM * 2);
}